// round 5
// baseline (speedup 1.0000x reference)
#include <cuda_runtime.h>
#include <cuda_bf16.h>
#include <math.h>

// ContrastLoss: feat [4,64,512,512] f32, gt [4,19,512,512] i32 -> scalar f32

#define NPIX  (4 * 262144)
#define HW    262144
#define KCLS  19
#define CCH   64
#define TAUF  0.07f
#define LOG2E 1.4426950408889634f

// -------- device scratch --------
__device__ float          g_k0[KCLS * CCH];
__device__ float          g_k0n[KCLS * CCH];
__device__ unsigned       g_maskbuf[NPIX];
__device__ int            g_numpos;
__device__ double         g_loss;

// -------- f32x2 helpers --------
__device__ __forceinline__ unsigned long long pack2(float a, float b) {
    unsigned long long r;
    asm("mov.b64 %0, {%1, %2};" : "=l"(r) : "f"(a), "f"(b));
    return r;
}
__device__ __forceinline__ void unpack2(unsigned long long v, float& a, float& b) {
    asm("mov.b64 {%0, %1}, %2;" : "=f"(a), "=f"(b) : "l"(v));
}
__device__ __forceinline__ void ffma2(unsigned long long& d, unsigned long long a,
                                      unsigned long long b) {
    asm("fma.rn.f32x2 %0, %1, %2, %0;" : "+l"(d) : "l"(a), "l"(b));
}
// predicated pair-add: if (m & bit) { accA += A; accB += B; }
__device__ __forceinline__ void padd2(unsigned long long& accA, unsigned long long& accB,
                                      unsigned m, unsigned bit,
                                      unsigned long long A, unsigned long long B) {
    asm("{\n\t"
        ".reg .pred p;\n\t"
        ".reg .u32 t;\n\t"
        "and.b32 t, %2, %3;\n\t"
        "setp.ne.u32 p, t, 0;\n\t"
        "@p add.rn.f32x2 %0, %0, %4;\n\t"
        "@p add.rn.f32x2 %1, %1, %5;\n\t"
        "}"
        : "+l"(accA), "+l"(accB)
        : "r"(m), "r"(bit), "l"(A), "l"(B));
}

// -------- kernel 0: zero accumulators --------
__global__ void k_zero() {
    int t = blockIdx.x * 256 + threadIdx.x;
    if (t < KCLS * CCH) g_k0[t] = 0.f;
    if (t == 0) { g_numpos = 0; g_loss = 0.0; }
}

// -------- kernel 1: build 19-bit pixel masks + num_pos (DRAM-bound) --------
__global__ __launch_bounds__(256) void k_mask(const int* __restrict__ gt) {
    const int p4 = (blockIdx.x * 256 + threadIdx.x) * 4;   // 1024 blocks exactly
    const int b  = p4 >> 18;
    const int hw = p4 & (HW - 1);
    unsigned m0 = 0, m1 = 0, m2 = 0, m3 = 0;
#pragma unroll
    for (int k = 0; k < KCLS; k++) {
        const int4 g = *reinterpret_cast<const int4*>(
            gt + (size_t)(b * KCLS + k) * HW + hw);
        m0 |= (unsigned)(g.x == 1) << k;
        m1 |= (unsigned)(g.y == 1) << k;
        m2 |= (unsigned)(g.z == 1) << k;
        m3 |= (unsigned)(g.w == 1) << k;
    }
    *reinterpret_cast<uint4*>(&g_maskbuf[p4]) = make_uint4(m0, m1, m2, m3);
    int cnt = __popc(m0) + __popc(m1) + __popc(m2) + __popc(m3);
#pragma unroll
    for (int o = 16; o; o >>= 1) cnt += __shfl_xor_sync(0xffffffffu, cnt, o);
    if ((threadIdx.x & 31) == 0) atomicAdd(&g_numpos, cnt);
}

// -------- kernel 2: prototype scatter-sum (predicated f32x2 adds) --------
// grid.y = 16 channel groups (channels 4g..4g+3). No shared in hot loop.
__global__ __launch_bounds__(256, 2) void k_proto(const float* __restrict__ feat) {
    const int g  = blockIdx.y;
    const int c0 = 4 * g;

    unsigned long long accA[KCLS], accB[KCLS];
#pragma unroll
    for (int k = 0; k < KCLS; k++) { accA[k] = 0ull; accB[k] = 0ull; }

    const int stride = gridDim.x * 256;
    for (int p = blockIdx.x * 256 + threadIdx.x; p < NPIX; p += stride) {
        const unsigned m = g_maskbuf[p];
        const int b  = p >> 18;
        const int hw = p & (HW - 1);
        const float* fb = feat + (size_t)(b * CCH + c0) * HW + hw;
        const float f0 = fb[0];
        const float f1 = fb[HW];
        const float f2 = fb[2 * HW];
        const float f3 = fb[3 * HW];
        const unsigned long long A = pack2(f0, f1);
        const unsigned long long B = pack2(f2, f3);
        if (m) {
#pragma unroll
            for (int k = 0; k < KCLS; k++)
                padd2(accA[k], accB[k], m, 1u << k, A, B);
        }
    }

    // reduce within block: warp shuffles, then shared atomics, then global atomic
    __shared__ float sh[KCLS * 4];
    for (int t = threadIdx.x; t < KCLS * 4; t += 256) sh[t] = 0.f;
    __syncthreads();

#pragma unroll
    for (int k = 0; k < KCLS; k++) {
        float a0, a1, a2, a3;
        unpack2(accA[k], a0, a1);
        unpack2(accB[k], a2, a3);
#pragma unroll
        for (int o = 16; o; o >>= 1) {
            a0 += __shfl_xor_sync(0xffffffffu, a0, o);
            a1 += __shfl_xor_sync(0xffffffffu, a1, o);
            a2 += __shfl_xor_sync(0xffffffffu, a2, o);
            a3 += __shfl_xor_sync(0xffffffffu, a3, o);
        }
        if ((threadIdx.x & 31) == 0) {
            atomicAdd(&sh[k * 4 + 0], a0);
            atomicAdd(&sh[k * 4 + 1], a1);
            atomicAdd(&sh[k * 4 + 2], a2);
            atomicAdd(&sh[k * 4 + 3], a3);
        }
    }
    __syncthreads();
    if (threadIdx.x < KCLS * 4) {
        const int k = threadIdx.x >> 2;
        const int c = threadIdx.x & 3;
        atomicAdd(&g_k0[k * CCH + c0 + c], sh[threadIdx.x]);
    }
}

// -------- kernel 3: normalize prototypes --------
__global__ void k_norm() {
    const int k    = threadIdx.x >> 5;
    const int lane = threadIdx.x & 31;
    if (k >= KCLS) return;
    const float v0 = g_k0[k * CCH + lane];
    const float v1 = g_k0[k * CCH + 32 + lane];
    float s = v0 * v0 + v1 * v1;
#pragma unroll
    for (int o = 16; o; o >>= 1) s += __shfl_xor_sync(0xffffffffu, s, o);
    const float inv = 1.f / fmaxf(sqrtf(s), 1e-12f);
    g_k0n[k * CCH + lane]      = v0 * inv;
    g_k0n[k * CCH + 32 + lane] = v1 * inv;
}

// -------- per-pixel softmax/NLL epilogue --------
__device__ __forceinline__ float pix_loss(const float* __restrict__ l,
                                          float ssum, unsigned m) {
    const float sc = 1.f / (fmaxf(sqrtf(ssum), 1e-12f) * TAUF);
    float v[KCLS];
    float mx = -1e30f;
#pragma unroll
    for (int k = 0; k < KCLS; k++) {
        v[k] = l[k] * sc;
        mx = fmaxf(mx, v[k]);
    }
    float se = 0.f, sl = 0.f;
#pragma unroll
    for (int k = 0; k < KCLS; k++) {
        se += exp2f((v[k] - mx) * LOG2E);
        if (m & (1u << k)) sl += v[k];
    }
    return (float)__popc(m) * (mx + logf(se)) - sl;
}

// -------- kernel 4: logits + log-softmax NLL, 2 px/thread (occupancy) --------
__global__ __launch_bounds__(256, 3) void k_loss(const float* __restrict__ feat) {
    __shared__ unsigned long long sknd[KCLS * CCH];     // (kn,kn) duplicated, 9.5 KB
    for (int t = threadIdx.x; t < KCLS * CCH; t += 256) {
        const float v = g_k0n[t];
        sknd[t] = pack2(v, v);
    }
    __syncthreads();

    const int p2 = (blockIdx.x * 256 + threadIdx.x) * 2;   // 2048 blocks exactly
    const uint2 m2 = *reinterpret_cast<const uint2*>(&g_maskbuf[p2]);
    const int   b  = p2 >> 18;
    const int   hw = p2 & (HW - 1);
    const float* fb = feat + (size_t)(b * CCH) * HW + hw;

    unsigned long long acc[KCLS];
#pragma unroll
    for (int k = 0; k < KCLS; k++) acc[k] = 0ull;
    unsigned long long ss = 0ull;

#pragma unroll 4
    for (int c2 = 0; c2 < 32; c2++) {
        const unsigned long long F0 =
            *reinterpret_cast<const unsigned long long*>(fb + (size_t)(2 * c2) * HW);
        const unsigned long long F1 =
            *reinterpret_cast<const unsigned long long*>(fb + (size_t)(2 * c2 + 1) * HW);
        ffma2(ss, F0, F0);
        ffma2(ss, F1, F1);
#pragma unroll
        for (int k = 0; k < KCLS; k++) {
            const ulonglong2 kd =
                *reinterpret_cast<const ulonglong2*>(&sknd[k * CCH + 2 * c2]);
            ffma2(acc[k], F0, kd.x);
            ffma2(acc[k], F1, kd.y);
        }
    }

    float s0, s1;
    unpack2(ss, s0, s1);
    float l0[KCLS], l1[KCLS];
#pragma unroll
    for (int k = 0; k < KCLS; k++) unpack2(acc[k], l0[k], l1[k]);

    float lsum = pix_loss(l0, s0, m2.x) + pix_loss(l1, s1, m2.y);

    // block reduction -> double atomic
#pragma unroll
    for (int o = 16; o; o >>= 1) lsum += __shfl_xor_sync(0xffffffffu, lsum, o);
    __shared__ float wsum[8];
    if ((threadIdx.x & 31) == 0) wsum[threadIdx.x >> 5] = lsum;
    __syncthreads();
    if (threadIdx.x < 8) {
        float v = wsum[threadIdx.x];
#pragma unroll
        for (int o = 4; o; o >>= 1) v += __shfl_xor_sync(0x000000ffu, v, o);
        if (threadIdx.x == 0) atomicAdd(&g_loss, (double)v);
    }
}

// -------- kernel 5: finalize --------
__global__ void k_fin(float* out) {
    const int np = g_numpos;
    out[0] = (float)(g_loss / (double)(np > 0 ? np : 1));
}

extern "C" void kernel_launch(void* const* d_in, const int* in_sizes, int n_in,
                              void* d_out, int out_size) {
    const float* feat = (const float*)d_in[0];
    const int*   gt   = (const int*)d_in[1];
    float*       out  = (float*)d_out;

    k_zero <<<5, 256>>>();
    k_mask <<<NPIX / (256 * 4), 256>>>(gt);
    {
        dim3 grid(74, 16, 1);
        k_proto<<<grid, 256>>>(feat);
    }
    k_norm <<<1, KCLS * 32>>>();
    k_loss <<<NPIX / (256 * 2), 256>>>(feat);
    k_fin  <<<1, 1>>>(out);
}

// round 6
// speedup vs baseline: 1.3142x; 1.3142x over previous
#include <cuda_runtime.h>
#include <cuda_bf16.h>
#include <math.h>

// ContrastLoss: feat [4,64,512,512] f32, gt [4,19,512,512] i32 -> scalar f32

#define NPIX  (4 * 262144)
#define HW    262144
#define KCLS  19
#define CCH   64
#define TAUF  0.07f
#define LOG2E 1.4426950408889634f

// -------- device scratch --------
__device__ float          g_k0[KCLS * CCH];
__device__ float          g_k0n[KCLS * CCH];
__device__ unsigned       g_maskbuf[NPIX];
__device__ int            g_numpos;
__device__ double         g_loss;

// -------- f32x2 helpers --------
__device__ __forceinline__ unsigned long long pack2(float a, float b) {
    unsigned long long r;
    asm("mov.b64 %0, {%1, %2};" : "=l"(r) : "f"(a), "f"(b));
    return r;
}
__device__ __forceinline__ unsigned long long dup32(unsigned x) {
    unsigned long long r;
    asm("mov.b64 %0, {%1, %1};" : "=l"(r) : "r"(x));
    return r;
}
__device__ __forceinline__ void unpack2(unsigned long long v, float& a, float& b) {
    asm("mov.b64 {%0, %1}, %2;" : "=f"(a), "=f"(b) : "l"(v));
}
__device__ __forceinline__ void ffma2(unsigned long long& d, unsigned long long a,
                                      unsigned long long b) {
    asm("fma.rn.f32x2 %0, %1, %2, %0;" : "+l"(d) : "l"(a), "l"(b));
}

// -------- kernel 0: zero accumulators --------
__global__ void k_zero() {
    int t = blockIdx.x * 256 + threadIdx.x;
    if (t < KCLS * CCH) g_k0[t] = 0.f;
    if (t == 0) { g_numpos = 0; g_loss = 0.0; }
}

// -------- kernel 1: build 19-bit pixel masks + num_pos (DRAM-bound) --------
__global__ __launch_bounds__(256) void k_mask(const int* __restrict__ gt) {
    const int p4 = (blockIdx.x * 256 + threadIdx.x) * 4;   // 1024 blocks exactly
    const int b  = p4 >> 18;
    const int hw = p4 & (HW - 1);
    unsigned m0 = 0, m1 = 0, m2 = 0, m3 = 0;
#pragma unroll
    for (int k = 0; k < KCLS; k++) {
        const int4 g = *reinterpret_cast<const int4*>(
            gt + (size_t)(b * KCLS + k) * HW + hw);
        m0 |= (unsigned)(g.x == 1) << k;
        m1 |= (unsigned)(g.y == 1) << k;
        m2 |= (unsigned)(g.z == 1) << k;
        m3 |= (unsigned)(g.w == 1) << k;
    }
    *reinterpret_cast<uint4*>(&g_maskbuf[p4]) = make_uint4(m0, m1, m2, m3);
    int cnt = __popc(m0) + __popc(m1) + __popc(m2) + __popc(m3);
#pragma unroll
    for (int o = 16; o; o >>= 1) cnt += __shfl_xor_sync(0xffffffffu, cnt, o);
    if ((threadIdx.x & 31) == 0) atomicAdd(&g_numpos, cnt);
}

// -------- kernel 2: prototype scatter-sum --------
// Branch-free, predicate-free: mask bit -> float bits (0x3F800000 or 0) via
// BFE+IMAD, duplicated into both f32x2 lanes, then unconditional FFMA2.
// grid.y = 16 channel groups (channels 4g..4g+3). No shared in the hot loop.
__global__ __launch_bounds__(256, 2) void k_proto(const float* __restrict__ feat) {
    const int g  = blockIdx.y;
    const int c0 = 4 * g;

    unsigned long long accA[KCLS], accB[KCLS];
#pragma unroll
    for (int k = 0; k < KCLS; k++) { accA[k] = 0ull; accB[k] = 0ull; }

    const int stride = gridDim.x * 256;
    for (int p = blockIdx.x * 256 + threadIdx.x; p < NPIX; p += stride) {
        const unsigned m = g_maskbuf[p];
        const int b  = p >> 18;
        const int hw = p & (HW - 1);
        const float* fb = feat + (size_t)(b * CCH + c0) * HW + hw;
        const float f0 = fb[0];
        const float f1 = fb[HW];
        const float f2 = fb[2 * HW];
        const float f3 = fb[3 * HW];
        const unsigned long long A = pack2(f0, f1);
        const unsigned long long B = pack2(f2, f3);
#pragma unroll
        for (int k = 0; k < KCLS; k++) {
            const unsigned fmb = ((m >> k) & 1u) * 0x3F800000u;  // 1.0f or 0.0f bits
            const unsigned long long fm2 = dup32(fmb);
            ffma2(accA[k], A, fm2);
            ffma2(accB[k], B, fm2);
        }
    }

    // reduce within block: warp shuffles, then shared atomics, then global atomic
    __shared__ float sh[KCLS * 4];
    for (int t = threadIdx.x; t < KCLS * 4; t += 256) sh[t] = 0.f;
    __syncthreads();

#pragma unroll
    for (int k = 0; k < KCLS; k++) {
        float a0, a1, a2, a3;
        unpack2(accA[k], a0, a1);
        unpack2(accB[k], a2, a3);
#pragma unroll
        for (int o = 16; o; o >>= 1) {
            a0 += __shfl_xor_sync(0xffffffffu, a0, o);
            a1 += __shfl_xor_sync(0xffffffffu, a1, o);
            a2 += __shfl_xor_sync(0xffffffffu, a2, o);
            a3 += __shfl_xor_sync(0xffffffffu, a3, o);
        }
        if ((threadIdx.x & 31) == 0) {
            atomicAdd(&sh[k * 4 + 0], a0);
            atomicAdd(&sh[k * 4 + 1], a1);
            atomicAdd(&sh[k * 4 + 2], a2);
            atomicAdd(&sh[k * 4 + 3], a3);
        }
    }
    __syncthreads();
    if (threadIdx.x < KCLS * 4) {
        const int k = threadIdx.x >> 2;
        const int c = threadIdx.x & 3;
        atomicAdd(&g_k0[k * CCH + c0 + c], sh[threadIdx.x]);
    }
}

// -------- kernel 3: normalize prototypes --------
__global__ void k_norm() {
    const int k    = threadIdx.x >> 5;
    const int lane = threadIdx.x & 31;
    if (k >= KCLS) return;
    const float v0 = g_k0[k * CCH + lane];
    const float v1 = g_k0[k * CCH + 32 + lane];
    float s = v0 * v0 + v1 * v1;
#pragma unroll
    for (int o = 16; o; o >>= 1) s += __shfl_xor_sync(0xffffffffu, s, o);
    const float inv = 1.f / fmaxf(sqrtf(s), 1e-12f);
    g_k0n[k * CCH + lane]      = v0 * inv;
    g_k0n[k * CCH + 32 + lane] = v1 * inv;
}

// -------- per-pixel softmax/NLL epilogue --------
__device__ __forceinline__ float pix_loss(const float* __restrict__ l,
                                          float ssum, unsigned m) {
    const float sc = 1.f / (fmaxf(sqrtf(ssum), 1e-12f) * TAUF);
    float v[KCLS];
    float mx = -1e30f;
#pragma unroll
    for (int k = 0; k < KCLS; k++) {
        v[k] = l[k] * sc;
        mx = fmaxf(mx, v[k]);
    }
    float se = 0.f, sl = 0.f;
#pragma unroll
    for (int k = 0; k < KCLS; k++) {
        se += exp2f((v[k] - mx) * LOG2E);
        if (m & (1u << k)) sl += v[k];
    }
    return (float)__popc(m) * (mx + logf(se)) - sl;
}

// -------- kernel 4: logits + log-softmax NLL (R2 config: 4 px/thread) --------
__global__ __launch_bounds__(256, 2) void k_loss(const float* __restrict__ feat) {
    __shared__ unsigned long long sknd[KCLS * CCH];     // (kn,kn) duplicated, 9.5 KB
    for (int t = threadIdx.x; t < KCLS * CCH; t += 256) {
        const float v = g_k0n[t];
        sknd[t] = pack2(v, v);
    }
    __syncthreads();

    const int p4 = (blockIdx.x * 256 + threadIdx.x) * 4;   // 1024 blocks exactly
    const uint4 m  = *reinterpret_cast<const uint4*>(&g_maskbuf[p4]);
    const int   b  = p4 >> 18;
    const int   hw = p4 & (HW - 1);
    const float* fb = feat + (size_t)(b * CCH) * HW + hw;

    unsigned long long acca[KCLS], accb[KCLS];
#pragma unroll
    for (int k = 0; k < KCLS; k++) { acca[k] = 0ull; accb[k] = 0ull; }
    unsigned long long ssa = 0ull, ssb = 0ull;

#pragma unroll 2
    for (int c4 = 0; c4 < 16; c4++) {
        const float4 f0 = *reinterpret_cast<const float4*>(fb + (size_t)(4 * c4 + 0) * HW);
        const float4 f1 = *reinterpret_cast<const float4*>(fb + (size_t)(4 * c4 + 1) * HW);
        const float4 f2 = *reinterpret_cast<const float4*>(fb + (size_t)(4 * c4 + 2) * HW);
        const float4 f3 = *reinterpret_cast<const float4*>(fb + (size_t)(4 * c4 + 3) * HW);
        const unsigned long long A0 = pack2(f0.x, f0.y), B0 = pack2(f0.z, f0.w);
        const unsigned long long A1 = pack2(f1.x, f1.y), B1 = pack2(f1.z, f1.w);
        const unsigned long long A2 = pack2(f2.x, f2.y), B2 = pack2(f2.z, f2.w);
        const unsigned long long A3 = pack2(f3.x, f3.y), B3 = pack2(f3.z, f3.w);
        ffma2(ssa, A0, A0); ffma2(ssb, B0, B0);
        ffma2(ssa, A1, A1); ffma2(ssb, B1, B1);
        ffma2(ssa, A2, A2); ffma2(ssb, B2, B2);
        ffma2(ssa, A3, A3); ffma2(ssb, B3, B3);
#pragma unroll
        for (int k = 0; k < KCLS; k++) {
            const ulonglong2 k01 =
                *reinterpret_cast<const ulonglong2*>(&sknd[k * CCH + 4 * c4]);
            const ulonglong2 k23 =
                *reinterpret_cast<const ulonglong2*>(&sknd[k * CCH + 4 * c4 + 2]);
            ffma2(acca[k], A0, k01.x); ffma2(accb[k], B0, k01.x);
            ffma2(acca[k], A1, k01.y); ffma2(accb[k], B1, k01.y);
            ffma2(acca[k], A2, k23.x); ffma2(accb[k], B2, k23.x);
            ffma2(acca[k], A3, k23.y); ffma2(accb[k], B3, k23.y);
        }
    }

    float s0, s1, s2, s3;
    unpack2(ssa, s0, s1);
    unpack2(ssb, s2, s3);
    float l0[KCLS], l1[KCLS], l2[KCLS], l3[KCLS];
#pragma unroll
    for (int k = 0; k < KCLS; k++) {
        unpack2(acca[k], l0[k], l1[k]);
        unpack2(accb[k], l2[k], l3[k]);
    }
    float lsum = pix_loss(l0, s0, m.x) + pix_loss(l1, s1, m.y)
               + pix_loss(l2, s2, m.z) + pix_loss(l3, s3, m.w);

    // block reduction -> double atomic
#pragma unroll
    for (int o = 16; o; o >>= 1) lsum += __shfl_xor_sync(0xffffffffu, lsum, o);
    __shared__ float wsum[8];
    if ((threadIdx.x & 31) == 0) wsum[threadIdx.x >> 5] = lsum;
    __syncthreads();
    if (threadIdx.x < 8) {
        float v = wsum[threadIdx.x];
#pragma unroll
        for (int o = 4; o; o >>= 1) v += __shfl_xor_sync(0x000000ffu, v, o);
        if (threadIdx.x == 0) atomicAdd(&g_loss, (double)v);
    }
}

// -------- kernel 5: finalize --------
__global__ void k_fin(float* out) {
    const int np = g_numpos;
    out[0] = (float)(g_loss / (double)(np > 0 ? np : 1));
}

extern "C" void kernel_launch(void* const* d_in, const int* in_sizes, int n_in,
                              void* d_out, int out_size) {
    const float* feat = (const float*)d_in[0];
    const int*   gt   = (const int*)d_in[1];
    float*       out  = (float*)d_out;

    k_zero <<<5, 256>>>();
    k_mask <<<NPIX / (256 * 4), 256>>>(gt);
    {
        dim3 grid(74, 16, 1);
        k_proto<<<grid, 256>>>(feat);
    }
    k_norm <<<1, KCLS * 32>>>();
    k_loss <<<NPIX / (256 * 4), 256>>>(feat);
    k_fin  <<<1, 1>>>(out);
}

// round 7
// speedup vs baseline: 1.3285x; 1.0109x over previous
#include <cuda_runtime.h>
#include <cuda_bf16.h>
#include <math.h>

// ContrastLoss: feat [4,64,512,512] f32, gt [4,19,512,512] i32 -> scalar f32

#define NPIX  (4 * 262144)
#define HW    262144
#define KCLS  19
#define CCH   64
#define TAUF  0.07f
#define LOG2E 1.4426950408889634f

// -------- device scratch --------
__device__ float          g_k0[KCLS * CCH];
__device__ unsigned       g_maskbuf[NPIX];
__device__ int            g_cnt[1024];
__device__ double         g_loss;

// -------- f32x2 helpers --------
__device__ __forceinline__ unsigned long long pack2(float a, float b) {
    unsigned long long r;
    asm("mov.b64 %0, {%1, %2};" : "=l"(r) : "f"(a), "f"(b));
    return r;
}
__device__ __forceinline__ void unpack2(unsigned long long v, float& a, float& b) {
    asm("mov.b64 {%0, %1}, %2;" : "=f"(a), "=f"(b) : "l"(v));
}
__device__ __forceinline__ void ffma2(unsigned long long& d, unsigned long long a,
                                      unsigned long long b) {
    asm("fma.rn.f32x2 %0, %1, %2, %0;" : "+l"(d) : "l"(a), "l"(b));
}
// per-class: fm2 = dup( ((m>>k)&1) ? 1.0f : 0.0f ); acc{A,B} += {A,B}*fm2
// forced BFE + IMAD + MOV (3 alu ops) + 2 FFMA2
__device__ __forceinline__ void mclass(unsigned long long& accA, unsigned long long& accB,
                                       unsigned m, int k,
                                       unsigned long long A, unsigned long long B) {
    unsigned long long fm2;
    asm("{\n\t"
        ".reg .u32 b, f;\n\t"
        "bfe.u32 b, %1, %2, 1;\n\t"
        "mul.lo.u32 f, b, 0x3F800000;\n\t"
        "mov.b64 %0, {f, f};\n\t"
        "}" : "=l"(fm2) : "r"(m), "r"(k));
    ffma2(accA, A, fm2);
    ffma2(accB, B, fm2);
}

// -------- launch 0: zero prototype accumulator --------
__global__ void k_zero() {
    int t = blockIdx.x * 256 + threadIdx.x;
    if (t < KCLS * CCH) g_k0[t] = 0.f;
}

// -------- launch 1: build 19-bit pixel masks + per-block pos counts --------
__global__ __launch_bounds__(256) void k_mask(const int* __restrict__ gt) {
    const int p4 = (blockIdx.x * 256 + threadIdx.x) * 4;   // 1024 blocks exactly
    const int b  = p4 >> 18;
    const int hw = p4 & (HW - 1);
    unsigned m0 = 0, m1 = 0, m2 = 0, m3 = 0;
#pragma unroll
    for (int k = 0; k < KCLS; k++) {
        const int4 g = *reinterpret_cast<const int4*>(
            gt + (size_t)(b * KCLS + k) * HW + hw);
        m0 |= (unsigned)(g.x == 1) << k;
        m1 |= (unsigned)(g.y == 1) << k;
        m2 |= (unsigned)(g.z == 1) << k;
        m3 |= (unsigned)(g.w == 1) << k;
    }
    *reinterpret_cast<uint4*>(&g_maskbuf[p4]) = make_uint4(m0, m1, m2, m3);
    int cnt = __popc(m0) + __popc(m1) + __popc(m2) + __popc(m3);
#pragma unroll
    for (int o = 16; o; o >>= 1) cnt += __shfl_xor_sync(0xffffffffu, cnt, o);
    __shared__ int sc[8];
    if ((threadIdx.x & 31) == 0) sc[threadIdx.x >> 5] = cnt;
    __syncthreads();
    if (threadIdx.x == 0) {
        int s = 0;
#pragma unroll
        for (int w = 0; w < 8; w++) s += sc[w];
        g_cnt[blockIdx.x] = s;
    }
}

// -------- launch 2: zero loss accumulator (also spaces the profile window) --------
__global__ void k_zero2() {
    if (threadIdx.x == 0) g_loss = 0.0;
}

// -------- launch 3: prototype scatter-sum (PROFILED SLOT) --------
// grid.y = 16 channel groups (channels 4g..4g+3). No shared in the hot loop.
__global__ __launch_bounds__(256, 2) void k_proto(const float* __restrict__ feat) {
    const int g  = blockIdx.y;
    const int c0 = 4 * g;

    unsigned long long accA[KCLS], accB[KCLS];
#pragma unroll
    for (int k = 0; k < KCLS; k++) { accA[k] = 0ull; accB[k] = 0ull; }

    const int stride = gridDim.x * 256;
#pragma unroll 2
    for (int p = blockIdx.x * 256 + threadIdx.x; p < NPIX; p += stride) {
        const unsigned m = g_maskbuf[p];
        const int b  = p >> 18;
        const int hw = p & (HW - 1);
        const float* fb = feat + (size_t)(b * CCH + c0) * HW + hw;
        const float f0 = fb[0];
        const float f1 = fb[HW];
        const float f2 = fb[2 * HW];
        const float f3 = fb[3 * HW];
        const unsigned long long A = pack2(f0, f1);
        const unsigned long long B = pack2(f2, f3);
#pragma unroll
        for (int k = 0; k < KCLS; k++)
            mclass(accA[k], accB[k], m, k, A, B);
    }

    // reduce within block: warp shuffles, then shared atomics, then global atomic
    __shared__ float sh[KCLS * 4];
    for (int t = threadIdx.x; t < KCLS * 4; t += 256) sh[t] = 0.f;
    __syncthreads();

#pragma unroll
    for (int k = 0; k < KCLS; k++) {
        float a0, a1, a2, a3;
        unpack2(accA[k], a0, a1);
        unpack2(accB[k], a2, a3);
#pragma unroll
        for (int o = 16; o; o >>= 1) {
            a0 += __shfl_xor_sync(0xffffffffu, a0, o);
            a1 += __shfl_xor_sync(0xffffffffu, a1, o);
            a2 += __shfl_xor_sync(0xffffffffu, a2, o);
            a3 += __shfl_xor_sync(0xffffffffu, a3, o);
        }
        if ((threadIdx.x & 31) == 0) {
            atomicAdd(&sh[k * 4 + 0], a0);
            atomicAdd(&sh[k * 4 + 1], a1);
            atomicAdd(&sh[k * 4 + 2], a2);
            atomicAdd(&sh[k * 4 + 3], a3);
        }
    }
    __syncthreads();
    if (threadIdx.x < KCLS * 4) {
        const int k = threadIdx.x >> 2;
        const int c = threadIdx.x & 3;
        atomicAdd(&g_k0[k * CCH + c0 + c], sh[threadIdx.x]);
    }
}

// -------- per-pixel softmax/NLL epilogue (tau pre-folded into prototypes) --------
__device__ __forceinline__ float pix_loss(const float* __restrict__ l,
                                          float ssum, unsigned m) {
    const float sc = 1.f / fmaxf(sqrtf(ssum), 1e-12f);
    float v[KCLS];
    float mx = -1e30f;
#pragma unroll
    for (int k = 0; k < KCLS; k++) {
        v[k] = l[k] * sc;
        mx = fmaxf(mx, v[k]);
    }
    float se = 0.f, sl = 0.f;
#pragma unroll
    for (int k = 0; k < KCLS; k++) {
        se += exp2f((v[k] - mx) * LOG2E);
        if (m & (1u << k)) sl += v[k];
    }
    return (float)__popc(m) * (mx + logf(se)) - sl;
}

// -------- launch 4: logits + log-softmax NLL (4 px/thread, measured config) --------
__global__ __launch_bounds__(256, 2) void k_loss(const float* __restrict__ feat) {
    __shared__ unsigned long long sknd[KCLS * CCH];     // (kn/tau, kn/tau) duplicated
    __shared__ float sinv[KCLS];
    if (threadIdx.x < KCLS) {
        float s = 0.f;
#pragma unroll
        for (int c = 0; c < CCH; c++) {
            const float v = g_k0[threadIdx.x * CCH + c];
            s = fmaf(v, v, s);
        }
        sinv[threadIdx.x] = 1.f / (fmaxf(sqrtf(s), 1e-12f) * TAUF);
    }
    __syncthreads();
    for (int t = threadIdx.x; t < KCLS * CCH; t += 256) {
        const float v = g_k0[t] * sinv[t >> 6];
        sknd[t] = pack2(v, v);
    }
    __syncthreads();

    const int p4 = (blockIdx.x * 256 + threadIdx.x) * 4;   // 1024 blocks exactly
    const uint4 m  = *reinterpret_cast<const uint4*>(&g_maskbuf[p4]);
    const int   b  = p4 >> 18;
    const int   hw = p4 & (HW - 1);
    const float* fb = feat + (size_t)(b * CCH) * HW + hw;

    unsigned long long acca[KCLS], accb[KCLS];
#pragma unroll
    for (int k = 0; k < KCLS; k++) { acca[k] = 0ull; accb[k] = 0ull; }
    unsigned long long ssa = 0ull, ssb = 0ull;

#pragma unroll 2
    for (int c4 = 0; c4 < 16; c4++) {
        const float4 f0 = *reinterpret_cast<const float4*>(fb + (size_t)(4 * c4 + 0) * HW);
        const float4 f1 = *reinterpret_cast<const float4*>(fb + (size_t)(4 * c4 + 1) * HW);
        const float4 f2 = *reinterpret_cast<const float4*>(fb + (size_t)(4 * c4 + 2) * HW);
        const float4 f3 = *reinterpret_cast<const float4*>(fb + (size_t)(4 * c4 + 3) * HW);
        const unsigned long long A0 = pack2(f0.x, f0.y), B0 = pack2(f0.z, f0.w);
        const unsigned long long A1 = pack2(f1.x, f1.y), B1 = pack2(f1.z, f1.w);
        const unsigned long long A2 = pack2(f2.x, f2.y), B2 = pack2(f2.z, f2.w);
        const unsigned long long A3 = pack2(f3.x, f3.y), B3 = pack2(f3.z, f3.w);
        ffma2(ssa, A0, A0); ffma2(ssb, B0, B0);
        ffma2(ssa, A1, A1); ffma2(ssb, B1, B1);
        ffma2(ssa, A2, A2); ffma2(ssb, B2, B2);
        ffma2(ssa, A3, A3); ffma2(ssb, B3, B3);
#pragma unroll
        for (int k = 0; k < KCLS; k++) {
            const ulonglong2 k01 =
                *reinterpret_cast<const ulonglong2*>(&sknd[k * CCH + 4 * c4]);
            const ulonglong2 k23 =
                *reinterpret_cast<const ulonglong2*>(&sknd[k * CCH + 4 * c4 + 2]);
            ffma2(acca[k], A0, k01.x); ffma2(accb[k], B0, k01.x);
            ffma2(acca[k], A1, k01.y); ffma2(accb[k], B1, k01.y);
            ffma2(acca[k], A2, k23.x); ffma2(accb[k], B2, k23.x);
            ffma2(acca[k], A3, k23.y); ffma2(accb[k], B3, k23.y);
        }
    }

    float s0, s1, s2, s3;
    unpack2(ssa, s0, s1);
    unpack2(ssb, s2, s3);
    float l0[KCLS], l1[KCLS], l2[KCLS], l3[KCLS];
#pragma unroll
    for (int k = 0; k < KCLS; k++) {
        unpack2(acca[k], l0[k], l1[k]);
        unpack2(accb[k], l2[k], l3[k]);
    }
    float lsum = pix_loss(l0, s0, m.x) + pix_loss(l1, s1, m.y)
               + pix_loss(l2, s2, m.z) + pix_loss(l3, s3, m.w);

    // block reduction -> double atomic
#pragma unroll
    for (int o = 16; o; o >>= 1) lsum += __shfl_xor_sync(0xffffffffu, lsum, o);
    __shared__ float wsum[8];
    if ((threadIdx.x & 31) == 0) wsum[threadIdx.x >> 5] = lsum;
    __syncthreads();
    if (threadIdx.x < 8) {
        float v = wsum[threadIdx.x];
#pragma unroll
        for (int o = 4; o; o >>= 1) v += __shfl_xor_sync(0x000000ffu, v, o);
        if (threadIdx.x == 0) atomicAdd(&g_loss, (double)v);
    }
}

// -------- launch 5: finalize (sum per-block counts, divide) --------
__global__ void k_fin(float* out) {
    int s = 0;
    for (int t = threadIdx.x; t < 1024; t += 256) s += g_cnt[t];
#pragma unroll
    for (int o = 16; o; o >>= 1) s += __shfl_xor_sync(0xffffffffu, s, o);
    __shared__ int ws[8];
    if ((threadIdx.x & 31) == 0) ws[threadIdx.x >> 5] = s;
    __syncthreads();
    if (threadIdx.x == 0) {
        int np = 0;
#pragma unroll
        for (int w = 0; w < 8; w++) np += ws[w];
        out[0] = (float)(g_loss / (double)(np > 0 ? np : 1));
    }
}

extern "C" void kernel_launch(void* const* d_in, const int* in_sizes, int n_in,
                              void* d_out, int out_size) {
    const float* feat = (const float*)d_in[0];
    const int*   gt   = (const int*)d_in[1];
    float*       out  = (float*)d_out;

    k_zero <<<5, 256>>>();
    k_mask <<<NPIX / (256 * 4), 256>>>(gt);
    k_zero2<<<1, 32>>>();
    {
        dim3 grid(74, 16, 1);
        k_proto<<<grid, 256>>>(feat);
    }
    k_loss <<<NPIX / (256 * 4), 256>>>(feat);
    k_fin  <<<1, 256>>>(out);
}

// round 9
// speedup vs baseline: 1.3531x; 1.0186x over previous
#include <cuda_runtime.h>
#include <cuda_bf16.h>
#include <math.h>
#include <stdint.h>

// ContrastLoss: feat [4,64,512,512] f32, gt [4,19,512,512] i32 -> scalar f32

#define NPIX   (4 * 262144)
#define HW     262144
#define KCLS   19
#define CCH    64
#define TAUF   0.07f
#define LOG2E  1.4426950408889634f

// -------- device scratch --------
__device__ float    g_k0[KCLS * CCH];
__device__ unsigned g_maskbuf[NPIX];
__device__ int      g_cnt[1024];
__device__ double   g_loss;

// ======== f32x2 helpers ========
__device__ __forceinline__ unsigned long long pack2(float a, float b) {
    unsigned long long r;
    asm("mov.b64 %0, {%1, %2};" : "=l"(r) : "f"(a), "f"(b));
    return r;
}
__device__ __forceinline__ void unpack2(unsigned long long v, float& a, float& b) {
    asm("mov.b64 {%0, %1}, %2;" : "=f"(a), "=f"(b) : "l"(v));
}
__device__ __forceinline__ void ffma2(unsigned long long& d, unsigned long long a,
                                      unsigned long long b) {
    asm("fma.rn.f32x2 %0, %1, %2, %0;" : "+l"(d) : "l"(a), "l"(b));
}

// ======== bf16 hi/lo pack: low16 = bf16(f), high16 = bf16(f - float(bf16(f))) ====
__device__ __forceinline__ uint32_t hilo(float f) {
    uint32_t h;
    asm("cvt.rn.bf16x2.f32 %0, %1, %2;" : "=r"(h) : "f"(0.f), "f"(f)); // lower=bf16(f)
    const float hf = __uint_as_float(h << 16);
    const float lo = f - hf;
    uint32_t r;
    asm("cvt.rn.bf16x2.f32 %0, %1, %2;" : "=r"(r) : "f"(lo), "f"(f)); // upper=bf16(lo)
    return r;
}

// ======== warp MMA m16n8k16 bf16 (plain PTX, no sm_103a features) ========
__device__ __forceinline__ void mma16816(float* d, uint32_t a0, uint32_t a1,
                                         uint32_t a2, uint32_t a3,
                                         uint32_t b0, uint32_t b1) {
    asm volatile(
        "mma.sync.aligned.m16n8k16.row.col.f32.bf16.bf16.f32 "
        "{%0,%1,%2,%3}, {%4,%5,%6,%7}, {%8,%9}, {%0,%1,%2,%3};"
        : "+f"(d[0]), "+f"(d[1]), "+f"(d[2]), "+f"(d[3])
        : "r"(a0), "r"(a1), "r"(a2), "r"(a3), "r"(b0), "r"(b1));
}

// -------- launch 0: zero prototype accumulator --------
__global__ void k_zero() {
    int t = blockIdx.x * 256 + threadIdx.x;
    if (t < KCLS * CCH) g_k0[t] = 0.f;
}

// -------- launch 1: build 19-bit pixel masks + per-block pos counts --------
__global__ __launch_bounds__(256) void k_mask(const int* __restrict__ gt) {
    const int p4 = (blockIdx.x * 256 + threadIdx.x) * 4;   // 1024 blocks exactly
    const int b  = p4 >> 18;
    const int hw = p4 & (HW - 1);
    unsigned m0 = 0, m1 = 0, m2 = 0, m3 = 0;
#pragma unroll
    for (int k = 0; k < KCLS; k++) {
        const int4 g = *reinterpret_cast<const int4*>(
            gt + (size_t)(b * KCLS + k) * HW + hw);
        m0 |= (unsigned)(g.x == 1) << k;
        m1 |= (unsigned)(g.y == 1) << k;
        m2 |= (unsigned)(g.z == 1) << k;
        m3 |= (unsigned)(g.w == 1) << k;
    }
    *reinterpret_cast<uint4*>(&g_maskbuf[p4]) = make_uint4(m0, m1, m2, m3);
    int cnt = __popc(m0) + __popc(m1) + __popc(m2) + __popc(m3);
#pragma unroll
    for (int o = 16; o; o >>= 1) cnt += __shfl_xor_sync(0xffffffffu, cnt, o);
    __shared__ int sc[8];
    if ((threadIdx.x & 31) == 0) sc[threadIdx.x >> 5] = cnt;
    __syncthreads();
    if (threadIdx.x == 0) {
        int s = 0;
#pragma unroll
        for (int w = 0; w < 8; w++) s += sc[w];
        g_cnt[blockIdx.x] = s;
    }
}

// -------- launch 2: zero loss accumulator --------
__global__ void k_zero2() {
    if (threadIdx.x == 0) g_loss = 0.0;
}

// -------- launch 3: prototype scatter-sum via warp HMMA bf16 (PROFILED) --------
// k0[cls][ch] = sum_px mask * feat. A[16ch rows][K=16: (hi,lo)x8px], B[n=8cls][K].
// Warp w: channels (w&3)*16..+15, pixel slice (w>>2)*8 within a 16-px chunk.
// 3 n-frags cover classes 0..23 (mask bits 19..23 are zero -> exact).
__global__ __launch_bounds__(256) void k_proto_mma(const float* __restrict__ feat) {
    __shared__ float sk0[KCLS * CCH];
    const int tid  = threadIdx.x;
    const int w    = tid >> 5;
    const int lane = tid & 31;
    const int g    = lane >> 2;
    const int t    = lane & 3;
    const int chb  = (w & 3) * 16;
    const int sl   = w >> 2;

    for (int i = tid; i < KCLS * CCH; i += 256) sk0[i] = 0.f;
    __syncthreads();

    float d0[4] = {0.f, 0.f, 0.f, 0.f};
    float d1[4] = {0.f, 0.f, 0.f, 0.f};
    float d2[4] = {0.f, 0.f, 0.f, 0.f};

    const size_t r0 = (size_t)(chb + g) * HW;
    const size_t r1 = (size_t)(chb + g + 8) * HW;

    for (int chunk = blockIdx.x; chunk < NPIX / 16; chunk += gridDim.x) {
        const int px0 = chunk * 16 + sl * 8;
        const int b   = px0 >> 18;
        const int hw  = px0 & (HW - 1);
        const float* fb = feat + (size_t)(b * CCH) * HW + hw;

        const float f00 = fb[r0 + t];           // ch g,   px t
        const float f01 = fb[r0 + t + 4];       // ch g,   px t+4
        const float f10 = fb[r1 + t];           // ch g+8, px t
        const float f11 = fb[r1 + t + 4];       // ch g+8, px t+4
        const uint32_t a0 = hilo(f00);
        const uint32_t a1 = hilo(f10);
        const uint32_t a2 = hilo(f01);
        const uint32_t a3 = hilo(f11);

        const unsigned mA = g_maskbuf[px0 + t];
        const unsigned mB = g_maskbuf[px0 + t + 4];

        {   // classes 0..7
            const uint32_t b0 = ((mA >> g) & 1u) * 0x3F803F80u;
            const uint32_t b1 = ((mB >> g) & 1u) * 0x3F803F80u;
            mma16816(d0, a0, a1, a2, a3, b0, b1);
        }
        {   // classes 8..15
            const uint32_t b0 = ((mA >> (8 + g)) & 1u) * 0x3F803F80u;
            const uint32_t b1 = ((mB >> (8 + g)) & 1u) * 0x3F803F80u;
            mma16816(d1, a0, a1, a2, a3, b0, b1);
        }
        {   // classes 16..23 (19..23 always zero)
            const uint32_t b0 = ((mA >> (16 + g)) & 1u) * 0x3F803F80u;
            const uint32_t b1 = ((mB >> (16 + g)) & 1u) * 0x3F803F80u;
            mma16816(d2, a0, a1, a2, a3, b0, b1);
        }
    }

    // D lane(g,t): d[0]=D[g][2t], d[1]=D[g][2t+1], d[2]=D[g+8][2t], d[3]=D[g+8][2t+1]
    // rows are channels chb+g / chb+g+8, cols are classes 8f+2t(+1).
    {
        const int c0 = chb + g;
        const int c1 = chb + g + 8;
        const int k0c = 2 * t, k1c = 2 * t + 1;
        atomicAdd(&sk0[(k0c)      * CCH + c0], d0[0]);
        atomicAdd(&sk0[(k1c)      * CCH + c0], d0[1]);
        atomicAdd(&sk0[(k0c)      * CCH + c1], d0[2]);
        atomicAdd(&sk0[(k1c)      * CCH + c1], d0[3]);
        atomicAdd(&sk0[(8 + k0c)  * CCH + c0], d1[0]);
        atomicAdd(&sk0[(8 + k1c)  * CCH + c0], d1[1]);
        atomicAdd(&sk0[(8 + k0c)  * CCH + c1], d1[2]);
        atomicAdd(&sk0[(8 + k1c)  * CCH + c1], d1[3]);
        if (16 + k0c < KCLS) {
            atomicAdd(&sk0[(16 + k0c) * CCH + c0], d2[0]);
            atomicAdd(&sk0[(16 + k0c) * CCH + c1], d2[2]);
        }
        if (16 + k1c < KCLS) {
            atomicAdd(&sk0[(16 + k1c) * CCH + c0], d2[1]);
            atomicAdd(&sk0[(16 + k1c) * CCH + c1], d2[3]);
        }
    }
    __syncthreads();
    for (int i = tid; i < KCLS * CCH; i += 256) atomicAdd(&g_k0[i], sk0[i]);
}

// -------- per-pixel softmax/NLL epilogue (tau pre-folded into prototypes) --------
__device__ __forceinline__ float pix_loss(const float* __restrict__ l,
                                          float ssum, unsigned m) {
    const float sc = 1.f / fmaxf(sqrtf(ssum), 1e-12f);
    float v[KCLS];
    float mx = -1e30f;
#pragma unroll
    for (int k = 0; k < KCLS; k++) {
        v[k] = l[k] * sc;
        mx = fmaxf(mx, v[k]);
    }
    float se = 0.f, sl = 0.f;
#pragma unroll
    for (int k = 0; k < KCLS; k++) {
        se += exp2f((v[k] - mx) * LOG2E);
        if (m & (1u << k)) sl += v[k];
    }
    return (float)__popc(m) * (mx + logf(se)) - sl;
}

// -------- launch 4: logits + log-softmax NLL (4 px/thread) --------
__global__ __launch_bounds__(256, 2) void k_loss(const float* __restrict__ feat) {
    __shared__ unsigned long long sknd[KCLS * CCH];
    __shared__ float sinv[KCLS];
    if (threadIdx.x < KCLS) {
        float s = 0.f;
#pragma unroll
        for (int c = 0; c < CCH; c++) {
            const float v = g_k0[threadIdx.x * CCH + c];
            s = fmaf(v, v, s);
        }
        sinv[threadIdx.x] = 1.f / (fmaxf(sqrtf(s), 1e-12f) * TAUF);
    }
    __syncthreads();
    for (int t = threadIdx.x; t < KCLS * CCH; t += 256) {
        const float v = g_k0[t] * sinv[t >> 6];
        sknd[t] = pack2(v, v);
    }
    __syncthreads();

    const int p4 = (blockIdx.x * 256 + threadIdx.x) * 4;   // 1024 blocks exactly
    const uint4 m  = *reinterpret_cast<const uint4*>(&g_maskbuf[p4]);
    const int   b  = p4 >> 18;
    const int   hw = p4 & (HW - 1);
    const float* fb = feat + (size_t)(b * CCH) * HW + hw;

    unsigned long long acca[KCLS], accb[KCLS];
#pragma unroll
    for (int k = 0; k < KCLS; k++) { acca[k] = 0ull; accb[k] = 0ull; }
    unsigned long long ssa = 0ull, ssb = 0ull;

#pragma unroll 2
    for (int c4 = 0; c4 < 16; c4++) {
        const float4 f0 = *reinterpret_cast<const float4*>(fb + (size_t)(4 * c4 + 0) * HW);
        const float4 f1 = *reinterpret_cast<const float4*>(fb + (size_t)(4 * c4 + 1) * HW);
        const float4 f2 = *reinterpret_cast<const float4*>(fb + (size_t)(4 * c4 + 2) * HW);
        const float4 f3 = *reinterpret_cast<const float4*>(fb + (size_t)(4 * c4 + 3) * HW);
        const unsigned long long A0 = pack2(f0.x, f0.y), B0 = pack2(f0.z, f0.w);
        const unsigned long long A1 = pack2(f1.x, f1.y), B1 = pack2(f1.z, f1.w);
        const unsigned long long A2 = pack2(f2.x, f2.y), B2 = pack2(f2.z, f2.w);
        const unsigned long long A3 = pack2(f3.x, f3.y), B3 = pack2(f3.z, f3.w);
        ffma2(ssa, A0, A0); ffma2(ssb, B0, B0);
        ffma2(ssa, A1, A1); ffma2(ssb, B1, B1);
        ffma2(ssa, A2, A2); ffma2(ssb, B2, B2);
        ffma2(ssa, A3, A3); ffma2(ssb, B3, B3);
#pragma unroll
        for (int k = 0; k < KCLS; k++) {
            const ulonglong2 k01 =
                *reinterpret_cast<const ulonglong2*>(&sknd[k * CCH + 4 * c4]);
            const ulonglong2 k23 =
                *reinterpret_cast<const ulonglong2*>(&sknd[k * CCH + 4 * c4 + 2]);
            ffma2(acca[k], A0, k01.x); ffma2(accb[k], B0, k01.x);
            ffma2(acca[k], A1, k01.y); ffma2(accb[k], B1, k01.y);
            ffma2(acca[k], A2, k23.x); ffma2(accb[k], B2, k23.x);
            ffma2(acca[k], A3, k23.y); ffma2(accb[k], B3, k23.y);
        }
    }

    float s0, s1, s2, s3;
    unpack2(ssa, s0, s1);
    unpack2(ssb, s2, s3);
    float l0[KCLS], l1[KCLS], l2[KCLS], l3[KCLS];
#pragma unroll
    for (int k = 0; k < KCLS; k++) {
        unpack2(acca[k], l0[k], l1[k]);
        unpack2(accb[k], l2[k], l3[k]);
    }
    float lsum = pix_loss(l0, s0, m.x) + pix_loss(l1, s1, m.y)
               + pix_loss(l2, s2, m.z) + pix_loss(l3, s3, m.w);

#pragma unroll
    for (int o = 16; o; o >>= 1) lsum += __shfl_xor_sync(0xffffffffu, lsum, o);
    __shared__ float wsum[8];
    if ((threadIdx.x & 31) == 0) wsum[threadIdx.x >> 5] = lsum;
    __syncthreads();
    if (threadIdx.x < 8) {
        float v = wsum[threadIdx.x];
#pragma unroll
        for (int o = 4; o; o >>= 1) v += __shfl_xor_sync(0x000000ffu, v, o);
        if (threadIdx.x == 0) atomicAdd(&g_loss, (double)v);
    }
}

// -------- launch 5: finalize --------
__global__ void k_fin(float* out) {
    int s = 0;
    for (int t = threadIdx.x; t < 1024; t += 256) s += g_cnt[t];
#pragma unroll
    for (int o = 16; o; o >>= 1) s += __shfl_xor_sync(0xffffffffu, s, o);
    __shared__ int ws[8];
    if ((threadIdx.x & 31) == 0) ws[threadIdx.x >> 5] = s;
    __syncthreads();
    if (threadIdx.x == 0) {
        int np = 0;
#pragma unroll
        for (int w = 0; w < 8; w++) np += ws[w];
        out[0] = (float)(g_loss / (double)(np > 0 ? np : 1));
    }
}

extern "C" void kernel_launch(void* const* d_in, const int* in_sizes, int n_in,
                              void* d_out, int out_size) {
    const float* feat = (const float*)d_in[0];
    const int*   gt   = (const int*)d_in[1];
    float*       out  = (float*)d_out;

    k_zero     <<<5, 256>>>();
    k_mask     <<<NPIX / (256 * 4), 256>>>(gt);
    k_zero2    <<<1, 32>>>();
    k_proto_mma<<<592, 256>>>(feat);
    k_loss     <<<NPIX / (256 * 4), 256>>>(feat);
    k_fin      <<<1, 256>>>(out);
}

// round 10
// speedup vs baseline: 1.9049x; 1.4078x over previous
#include <cuda_runtime.h>
#include <cuda_bf16.h>
#include <math.h>
#include <stdint.h>

// ContrastLoss: feat [4,64,512,512] f32, gt [4,19,512,512] i32 -> scalar f32

#define NPIX   (4 * 262144)
#define HW     262144
#define KCLS   19
#define CCH    64
#define TAUF   0.07f
#define LOG2E  1.4426950408889634f
#define CH64   16384               // NPIX / 64 : number of 64-px chunks

// -------- device scratch --------
__device__ float    g_k0[KCLS * CCH];
__device__ unsigned g_maskbuf[NPIX];
__device__ int      g_cnt[1024];
__device__ double   g_loss;

// ======== f32x2 helpers ========
__device__ __forceinline__ unsigned long long pack2(float a, float b) {
    unsigned long long r;
    asm("mov.b64 %0, {%1, %2};" : "=l"(r) : "f"(a), "f"(b));
    return r;
}
__device__ __forceinline__ void unpack2(unsigned long long v, float& a, float& b) {
    asm("mov.b64 {%0, %1}, %2;" : "=f"(a), "=f"(b) : "l"(v));
}
__device__ __forceinline__ void ffma2(unsigned long long& d, unsigned long long a,
                                      unsigned long long b) {
    asm("fma.rn.f32x2 %0, %1, %2, %0;" : "+l"(d) : "l"(a), "l"(b));
}

// ======== bf16 hi/lo pack: low16 = bf16(f), high16 = bf16(f - float(bf16(f))) ====
__device__ __forceinline__ uint32_t hilo(float f) {
    uint32_t h;
    asm("cvt.rn.bf16x2.f32 %0, %1, %2;" : "=r"(h) : "f"(0.f), "f"(f));
    const float hf = __uint_as_float(h << 16);
    const float lo = f - hf;
    uint32_t r;
    asm("cvt.rn.bf16x2.f32 %0, %1, %2;" : "=r"(r) : "f"(lo), "f"(f));
    return r;
}

// ======== warp MMA m16n8k16 bf16 ========
__device__ __forceinline__ void mma16816(float* d, uint32_t a0, uint32_t a1,
                                         uint32_t a2, uint32_t a3,
                                         uint32_t b0, uint32_t b1) {
    asm volatile(
        "mma.sync.aligned.m16n8k16.row.col.f32.bf16.bf16.f32 "
        "{%0,%1,%2,%3}, {%4,%5,%6,%7}, {%8,%9}, {%0,%1,%2,%3};"
        : "+f"(d[0]), "+f"(d[1]), "+f"(d[2]), "+f"(d[3])
        : "r"(a0), "r"(a1), "r"(a2), "r"(a3), "r"(b0), "r"(b1));
}

// -------- launch 0: zero prototype accumulator --------
__global__ void k_zero() {
    int t = blockIdx.x * 256 + threadIdx.x;
    if (t < KCLS * CCH) g_k0[t] = 0.f;
}

// -------- launch 1: build 19-bit pixel masks + per-block pos counts --------
__global__ __launch_bounds__(256) void k_mask(const int* __restrict__ gt) {
    const int p4 = (blockIdx.x * 256 + threadIdx.x) * 4;   // 1024 blocks exactly
    const int b  = p4 >> 18;
    const int hw = p4 & (HW - 1);
    unsigned m0 = 0, m1 = 0, m2 = 0, m3 = 0;
#pragma unroll
    for (int k = 0; k < KCLS; k++) {
        const int4 g = *reinterpret_cast<const int4*>(
            gt + (size_t)(b * KCLS + k) * HW + hw);
        m0 |= (unsigned)(g.x == 1) << k;
        m1 |= (unsigned)(g.y == 1) << k;
        m2 |= (unsigned)(g.z == 1) << k;
        m3 |= (unsigned)(g.w == 1) << k;
    }
    *reinterpret_cast<uint4*>(&g_maskbuf[p4]) = make_uint4(m0, m1, m2, m3);
    int cnt = __popc(m0) + __popc(m1) + __popc(m2) + __popc(m3);
#pragma unroll
    for (int o = 16; o; o >>= 1) cnt += __shfl_xor_sync(0xffffffffu, cnt, o);
    __shared__ int sc[8];
    if ((threadIdx.x & 31) == 0) sc[threadIdx.x >> 5] = cnt;
    __syncthreads();
    if (threadIdx.x == 0) {
        int s = 0;
#pragma unroll
        for (int w = 0; w < 8; w++) s += sc[w];
        g_cnt[blockIdx.x] = s;
    }
}

// -------- launch 2: zero loss accumulator --------
__global__ void k_zero2() {
    if (threadIdx.x == 0) g_loss = 0.0;
}

// -------- launch 3: smem-staged HMMA prototype GEMM (PROFILED SLOT) --------
// Per 64-px chunk: stage [64ch x 64px] as hi/lo bf16x2 u32 into swizzled smem
// (coalesced LDG.128, conflict-free STS.128), then 8 warps run m16n8k16 MMAs.
// Warp w: channels (w&3)*16..+15, px half (w>>2)*32. K packing: K(2t,2t+1) =
// px p+2t (hi,lo), K(2t+8,2t+9) = px p+2t+1 -> A-pairs are LDS.64.
__global__ __launch_bounds__(256, 4) void k_proto_mma(const float* __restrict__ feat) {
    __shared__ uint32_t sA[64 * 80];     // [ch][80] u32, px swizzled by 8*(ch&3)
    __shared__ uint32_t sM[64];
    __shared__ float    sk0[KCLS * CCH];

    const int tid  = threadIdx.x;
    const int w    = tid >> 5;
    const int lane = tid & 31;
    const int g    = lane >> 2;
    const int t    = lane & 3;
    const int chb  = (w & 3) * 16;       // MMA channel base
    const int hb   = (w >> 2) * 32;      // MMA pixel half

    // stage mapping: 2 channels x 16 lanes per LDG.128 -> 4 full lines/instr
    const int sc_hi = lane >> 4;         // 0/1
    const int sc_px = (lane & 15) * 4;   // 0..60

    for (int i = tid; i < KCLS * CCH; i += 256) sk0[i] = 0.f;

    float d0[4] = {0.f, 0.f, 0.f, 0.f};
    float d1[4] = {0.f, 0.f, 0.f, 0.f};
    float d2[4] = {0.f, 0.f, 0.f, 0.f};

    for (int chunk = blockIdx.x; chunk < CH64; chunk += gridDim.x) {
        const int P  = chunk * 64;
        const int b  = P >> 18;
        const int hw = P & (HW - 1);
        __syncthreads();   // previous MMA stage done reading smem

        // ---- stage: LDG.128 -> hi/lo cvt -> swizzled STS.128 ----
#pragma unroll
        for (int i = 0; i < 4; i++) {
            const int ch = w * 8 + 2 * i + sc_hi;
            const float4 f = *reinterpret_cast<const float4*>(
                feat + (size_t)(b * CCH + ch) * HW + hw + sc_px);
            const uint32_t h0 = hilo(f.x);
            const uint32_t h1 = hilo(f.y);
            const uint32_t h2 = hilo(f.z);
            const uint32_t h3 = hilo(f.w);
            const int word = ch * 80 + (sc_px ^ ((ch & 3) << 3));
            *reinterpret_cast<uint4*>(&sA[word]) = make_uint4(h0, h1, h2, h3);
        }
        if (tid < 16)
            *reinterpret_cast<uint4*>(&sM[tid * 4]) =
                *reinterpret_cast<const uint4*>(&g_maskbuf[P + tid * 4]);
        __syncthreads();

        // ---- MMA: 4 K-steps x 3 class groups ----
#pragma unroll
        for (int s = 0; s < 4; s++) {
            const int px = hb + 8 * s + 2 * t;            // even
            const int sw = px ^ ((g & 3) << 3);
            const uint2 A0 = *reinterpret_cast<const uint2*>(&sA[(chb + g) * 80 + sw]);
            const uint2 A1 = *reinterpret_cast<const uint2*>(&sA[(chb + g + 8) * 80 + sw]);
            const uint2 M  = *reinterpret_cast<const uint2*>(&sM[px]);
            {
                const uint32_t b0 = ((M.x >> g) & 1u) * 0x3F803F80u;
                const uint32_t b1 = ((M.y >> g) & 1u) * 0x3F803F80u;
                mma16816(d0, A0.x, A1.x, A0.y, A1.y, b0, b1);
            }
            {
                const uint32_t b0 = ((M.x >> (8 + g)) & 1u) * 0x3F803F80u;
                const uint32_t b1 = ((M.y >> (8 + g)) & 1u) * 0x3F803F80u;
                mma16816(d1, A0.x, A1.x, A0.y, A1.y, b0, b1);
            }
            {
                const uint32_t b0 = ((M.x >> (16 + g)) & 1u) * 0x3F803F80u;
                const uint32_t b1 = ((M.y >> (16 + g)) & 1u) * 0x3F803F80u;
                mma16816(d2, A0.x, A1.x, A0.y, A1.y, b0, b1);
            }
        }
    }

    // ---- epilogue: D lane(g,t): d[0]=D[ch chb+g][cls 2t], d[1]=cls 2t+1,
    //      d[2]=D[ch chb+g+8][cls 2t], d[3]=cls 2t+1 (validated in R9) ----
    __syncthreads();
    {
        const int c0 = chb + g;
        const int c1 = chb + g + 8;
        const int k0c = 2 * t, k1c = 2 * t + 1;
        atomicAdd(&sk0[(k0c)     * CCH + c0], d0[0]);
        atomicAdd(&sk0[(k1c)     * CCH + c0], d0[1]);
        atomicAdd(&sk0[(k0c)     * CCH + c1], d0[2]);
        atomicAdd(&sk0[(k1c)     * CCH + c1], d0[3]);
        atomicAdd(&sk0[(8 + k0c) * CCH + c0], d1[0]);
        atomicAdd(&sk0[(8 + k1c) * CCH + c0], d1[1]);
        atomicAdd(&sk0[(8 + k0c) * CCH + c1], d1[2]);
        atomicAdd(&sk0[(8 + k1c) * CCH + c1], d1[3]);
        if (16 + k0c < KCLS) {
            atomicAdd(&sk0[(16 + k0c) * CCH + c0], d2[0]);
            atomicAdd(&sk0[(16 + k0c) * CCH + c1], d2[2]);
        }
        if (16 + k1c < KCLS) {
            atomicAdd(&sk0[(16 + k1c) * CCH + c0], d2[1]);
            atomicAdd(&sk0[(16 + k1c) * CCH + c1], d2[3]);
        }
    }
    __syncthreads();
    for (int i = tid; i < KCLS * CCH; i += 256) atomicAdd(&g_k0[i], sk0[i]);
}

// -------- per-pixel softmax/NLL epilogue (tau pre-folded into prototypes) --------
__device__ __forceinline__ float pix_loss(const float* __restrict__ l,
                                          float ssum, unsigned m) {
    const float sc = 1.f / fmaxf(sqrtf(ssum), 1e-12f);
    float v[KCLS];
    float mx = -1e30f;
#pragma unroll
    for (int k = 0; k < KCLS; k++) {
        v[k] = l[k] * sc;
        mx = fmaxf(mx, v[k]);
    }
    float se = 0.f, sl = 0.f;
#pragma unroll
    for (int k = 0; k < KCLS; k++) {
        se += exp2f((v[k] - mx) * LOG2E);
        if (m & (1u << k)) sl += v[k];
    }
    return (float)__popc(m) * (mx + logf(se)) - sl;
}

// -------- launch 4: logits + log-softmax NLL (4 px/thread) --------
__global__ __launch_bounds__(256, 2) void k_loss(const float* __restrict__ feat) {
    __shared__ unsigned long long sknd[KCLS * CCH];
    __shared__ float sinv[KCLS];
    if (threadIdx.x < KCLS) {
        float s = 0.f;
#pragma unroll
        for (int c = 0; c < CCH; c++) {
            const float v = g_k0[threadIdx.x * CCH + c];
            s = fmaf(v, v, s);
        }
        sinv[threadIdx.x] = 1.f / (fmaxf(sqrtf(s), 1e-12f) * TAUF);
    }
    __syncthreads();
    for (int t = threadIdx.x; t < KCLS * CCH; t += 256) {
        const float v = g_k0[t] * sinv[t >> 6];
        sknd[t] = pack2(v, v);
    }
    __syncthreads();

    const int p4 = (blockIdx.x * 256 + threadIdx.x) * 4;   // 1024 blocks exactly
    const uint4 m  = *reinterpret_cast<const uint4*>(&g_maskbuf[p4]);
    const int   b  = p4 >> 18;
    const int   hw = p4 & (HW - 1);
    const float* fb = feat + (size_t)(b * CCH) * HW + hw;

    unsigned long long acca[KCLS], accb[KCLS];
#pragma unroll
    for (int k = 0; k < KCLS; k++) { acca[k] = 0ull; accb[k] = 0ull; }
    unsigned long long ssa = 0ull, ssb = 0ull;

#pragma unroll 2
    for (int c4 = 0; c4 < 16; c4++) {
        const float4 f0 = *reinterpret_cast<const float4*>(fb + (size_t)(4 * c4 + 0) * HW);
        const float4 f1 = *reinterpret_cast<const float4*>(fb + (size_t)(4 * c4 + 1) * HW);
        const float4 f2 = *reinterpret_cast<const float4*>(fb + (size_t)(4 * c4 + 2) * HW);
        const float4 f3 = *reinterpret_cast<const float4*>(fb + (size_t)(4 * c4 + 3) * HW);
        const unsigned long long A0 = pack2(f0.x, f0.y), B0 = pack2(f0.z, f0.w);
        const unsigned long long A1 = pack2(f1.x, f1.y), B1 = pack2(f1.z, f1.w);
        const unsigned long long A2 = pack2(f2.x, f2.y), B2 = pack2(f2.z, f2.w);
        const unsigned long long A3 = pack2(f3.x, f3.y), B3 = pack2(f3.z, f3.w);
        ffma2(ssa, A0, A0); ffma2(ssb, B0, B0);
        ffma2(ssa, A1, A1); ffma2(ssb, B1, B1);
        ffma2(ssa, A2, A2); ffma2(ssb, B2, B2);
        ffma2(ssa, A3, A3); ffma2(ssb, B3, B3);
#pragma unroll
        for (int k = 0; k < KCLS; k++) {
            const ulonglong2 k01 =
                *reinterpret_cast<const ulonglong2*>(&sknd[k * CCH + 4 * c4]);
            const ulonglong2 k23 =
                *reinterpret_cast<const ulonglong2*>(&sknd[k * CCH + 4 * c4 + 2]);
            ffma2(acca[k], A0, k01.x); ffma2(accb[k], B0, k01.x);
            ffma2(acca[k], A1, k01.y); ffma2(accb[k], B1, k01.y);
            ffma2(acca[k], A2, k23.x); ffma2(accb[k], B2, k23.x);
            ffma2(acca[k], A3, k23.y); ffma2(accb[k], B3, k23.y);
        }
    }

    float s0, s1, s2, s3;
    unpack2(ssa, s0, s1);
    unpack2(ssb, s2, s3);
    float l0[KCLS], l1[KCLS], l2[KCLS], l3[KCLS];
#pragma unroll
    for (int k = 0; k < KCLS; k++) {
        unpack2(acca[k], l0[k], l1[k]);
        unpack2(accb[k], l2[k], l3[k]);
    }
    float lsum = pix_loss(l0, s0, m.x) + pix_loss(l1, s1, m.y)
               + pix_loss(l2, s2, m.z) + pix_loss(l3, s3, m.w);

#pragma unroll
    for (int o = 16; o; o >>= 1) lsum += __shfl_xor_sync(0xffffffffu, lsum, o);
    __shared__ float wsum[8];
    if ((threadIdx.x & 31) == 0) wsum[threadIdx.x >> 5] = lsum;
    __syncthreads();
    if (threadIdx.x < 8) {
        float v = wsum[threadIdx.x];
#pragma unroll
        for (int o = 4; o; o >>= 1) v += __shfl_xor_sync(0x000000ffu, v, o);
        if (threadIdx.x == 0) atomicAdd(&g_loss, (double)v);
    }
}

// -------- launch 5: finalize --------
__global__ void k_fin(float* out) {
    int s = 0;
    for (int t = threadIdx.x; t < 1024; t += 256) s += g_cnt[t];
#pragma unroll
    for (int o = 16; o; o >>= 1) s += __shfl_xor_sync(0xffffffffu, s, o);
    __shared__ int ws[8];
    if ((threadIdx.x & 31) == 0) ws[threadIdx.x >> 5] = s;
    __syncthreads();
    if (threadIdx.x == 0) {
        int np = 0;
#pragma unroll
        for (int w = 0; w < 8; w++) np += ws[w];
        out[0] = (float)(g_loss / (double)(np > 0 ? np : 1));
    }
}

extern "C" void kernel_launch(void* const* d_in, const int* in_sizes, int n_in,
                              void* d_out, int out_size) {
    const float* feat = (const float*)d_in[0];
    const int*   gt   = (const int*)d_in[1];
    float*       out  = (float*)d_out;

    k_zero     <<<5, 256>>>();
    k_mask     <<<NPIX / (256 * 4), 256>>>(gt);
    k_zero2    <<<1, 32>>>();
    k_proto_mma<<<592, 256>>>(feat);
    k_loss     <<<NPIX / (256 * 4), 256>>>(feat);
    k_fin      <<<1, 256>>>(out);
}